// round 8
// baseline (speedup 1.0000x reference)
#include <cuda_runtime.h>
#include <math.h>

#define BB 2
#define NN 4096
#define CD 64
#define NTH 128
#define MAXL 512

// output layout offsets (floats), concatenated in reference return order
#define EXPOFF  0ull
#define DISPOFF 24576ull
#define POFF    49152ull
#define CONFOFF 33603584ull
#define ENTOFF  33611776ull
#define SRCPOFF 33619968ull

// scratch
__device__ float g_ssq[BB*NN];
__device__ float g_tsq[BB*NN];
__device__ float g_tadd[BB*NN];    // lml_j - 0.1*tu_j folded
__device__ float g_smatch[BB*NN];
__device__ float g_sdt[(size_t)BB*NN*CD];
__device__ float g_tdt[(size_t)BB*NN*CD];

__device__ __forceinline__ float lin16(int v) {
    return (float)(2*v - 15) * (1.0f/15.0f);
}

__device__ __forceinline__ float warpRedMax(float v){
    #pragma unroll
    for (int o = 16; o; o >>= 1) v = fmaxf(v, __shfl_xor_sync(0xffffffffu, v, o));
    return v;
}
__device__ __forceinline__ float warpRedMin(float v){
    #pragma unroll
    for (int o = 16; o; o >>= 1) v = fminf(v, __shfl_xor_sync(0xffffffffu, v, o));
    return v;
}
__device__ __forceinline__ float warpRedSum(float v){
    #pragma unroll
    for (int o = 16; o; o >>= 1) v += __shfl_xor_sync(0xffffffffu, v, o);
    return v;
}
__device__ __forceinline__ int warpRedSumI(int v){
    #pragma unroll
    for (int o = 16; o; o >>= 1) v += __shfl_xor_sync(0xffffffffu, v, o);
    return v;
}

__device__ __forceinline__ float blockRedMax(float v, float* sred){
    v = warpRedMax(v);
    __syncthreads();
    if ((threadIdx.x & 31) == 0) sred[threadIdx.x >> 5] = v;
    __syncthreads();
    return fmaxf(fmaxf(sred[0], sred[1]), fmaxf(sred[2], sred[3]));
}
__device__ __forceinline__ float blockRedMin(float v, float* sred){
    v = warpRedMin(v);
    __syncthreads();
    if ((threadIdx.x & 31) == 0) sred[threadIdx.x >> 5] = v;
    __syncthreads();
    return fminf(fminf(sred[0], sred[1]), fminf(sred[2], sred[3]));
}
__device__ __forceinline__ float blockRedSum(float v, float* sred){
    v = warpRedSum(v);
    __syncthreads();
    if ((threadIdx.x & 31) == 0) sred[threadIdx.x >> 5] = v;
    __syncthreads();
    return (sred[0] + sred[1]) + (sred[2] + sred[3]);
}
__device__ __forceinline__ int blockRedSumI(int v, int* sred){
    v = warpRedSumI(v);
    __syncthreads();
    if ((threadIdx.x & 31) == 0) sred[threadIdx.x >> 5] = v;
    __syncthreads();
    return (sred[0] + sred[1]) + (sred[2] + sred[3]);
}

__global__ __launch_bounds__(256)
void kprep(const float* __restrict__ srcc, const float* __restrict__ tgtc,
           const float* __restrict__ sdesc, const float* __restrict__ tdesc,
           const float* __restrict__ sml, const float* __restrict__ tml,
           const float* __restrict__ tunc,
           float* __restrict__ out_srcpos)
{
    int idx = blockIdx.x * blockDim.x + threadIdx.x;
    if (idx >= BB*NN) return;
    int b = idx / NN, n = idx % NN;

    const float* scp = srcc + (size_t)b*3*NN;
    float s0 = scp[n], s1 = scp[NN+n], s2 = scp[2*NN+n];
    g_ssq[idx] = fmaf(s2, s2, fmaf(s1, s1, s0*s0));

    const float* tcp = tgtc + (size_t)b*3*NN;
    float t0 = tcp[n], t1 = tcp[NN+n], t2 = tcp[2*NN+n];
    g_tsq[idx] = fmaf(t2, t2, fmaf(t1, t1, t0*t0));

    const float* sm = sml + (size_t)b*2*NN;
    g_smatch[idx] = 1.0f / (1.0f + expf(sm[NN+n] - sm[n]));
    const float* tm = tml + (size_t)b*2*NN;
    float p0 = 1.0f / (1.0f + expf(tm[NN+n] - tm[n]));
    g_tadd[idx] = fmaxf(logf(p0), -20.0f) - 0.1f * tunc[idx];

    // transpose descriptors: (B,C,N) -> (B,N,C) row-major, float4 writes
    const float* sdp = sdesc + (size_t)b*CD*NN + n;
    const float* tdp = tdesc + (size_t)b*CD*NN + n;
    float4* so = (float4*)(g_sdt + (size_t)idx*CD);
    float4* to = (float4*)(g_tdt + (size_t)idx*CD);
    #pragma unroll
    for (int c4 = 0; c4 < CD/4; c4++) {
        float4 v, w;
        v.x = sdp[(size_t)(4*c4+0)*NN]; w.x = tdp[(size_t)(4*c4+0)*NN];
        v.y = sdp[(size_t)(4*c4+1)*NN]; w.y = tdp[(size_t)(4*c4+1)*NN];
        v.z = sdp[(size_t)(4*c4+2)*NN]; w.z = tdp[(size_t)(4*c4+2)*NN];
        v.w = sdp[(size_t)(4*c4+3)*NN]; w.w = tdp[(size_t)(4*c4+3)*NN];
        so[c4] = v;
        to[c4] = w;
    }

    // src_pos output (constant voxel grid broadcast)
    int d = n >> 8, h = (n >> 4) & 15, w = n & 15;
    out_srcpos[(size_t)idx*3 + 0] = lin16(d);
    out_srcpos[(size_t)idx*3 + 1] = lin16(h);
    out_srcpos[(size_t)idx*3 + 2] = lin16(w);
}

// processes rows i0 = 2*blockIdx.x and i0+1, sharing the tc/tsq stream
__global__ __launch_bounds__(NTH)
void kmain(const float* __restrict__ srcc, const float* __restrict__ tgtc,
           float* __restrict__ out, float radThr)
{
    const int i0 = 2 * blockIdx.x;
    const int b = blockIdx.y;
    const int t = threadIdx.x;
    const int lane = t & 31;
    const int warp = t >> 5;
    const int bi0 = b*NN + i0;

    __shared__ float s_v[2*NN];        // d2 rows for i0, i0+1 (clamped)
    __shared__ float s_sd[2*CD];       // descriptors for both rows
    __shared__ float s_red[4];
    __shared__ int   s_redi[4];
    __shared__ int   s_w[4];
    __shared__ int   s_list[MAXL];
    __shared__ float s_dist[MAXL];
    __shared__ float s_scr[MAXL];

    // ---- phase 0: zero both probs rows (contiguous 32KB, coalesced) ----
    float* prow0 = out + POFF + (size_t)bi0 * NN;
    {
        float4 z4 = make_float4(0.f, 0.f, 0.f, 0.f);
        float4* p4 = (float4*)prow0;
        #pragma unroll
        for (int s = 0; s < 16; s++) p4[t + s*NTH] = z4;
    }

    // both rows' descriptors are contiguous: 128 floats
    s_sd[t] = g_sdt[(size_t)bi0*CD + t];

    float sa0 = srcc[(size_t)b*3*NN + i0];
    float sa1 = srcc[(size_t)b*3*NN + NN + i0];
    float sa2 = srcc[(size_t)b*3*NN + 2*NN + i0];
    float sb0 = srcc[(size_t)b*3*NN + i0 + 1];
    float sb1 = srcc[(size_t)b*3*NN + NN + i0 + 1];
    float sb2 = srcc[(size_t)b*3*NN + 2*NN + i0 + 1];
    float ssqA = g_ssq[bi0];
    float ssqB = g_ssq[bi0 + 1];

    const float* tcp  = tgtc + (size_t)b*3*NN;
    const float* tsqp = g_tsq + b*NN;

    // ---- phase 1: shared stream, two d2 rows -> smem, packed radius counts --
    int myCnt = 0;                 // cntA in low 16, cntB in high 16
    #pragma unroll 8
    for (int s = 0; s < 32; s++) {
        int j = t + s*NTH;
        float u0 = tcp[j], u1 = tcp[NN+j], u2 = tcp[2*NN+j];
        float tq = tsqp[j];
        float dotA = fmaf(sa2, u2, fmaf(sa1, u1, sa0*u0));
        float dotB = fmaf(sb2, u2, fmaf(sb1, u1, sb0*u0));
        float d2A  = fmaxf(fmaf(-2.0f, dotA, ssqA + tq), 1e-12f);
        float d2B  = fmaxf(fmaf(-2.0f, dotB, ssqB + tq), 1e-12f);
        s_v[j]      = d2A;
        s_v[NN + j] = d2B;
        if (d2A <= radThr) myCnt++;
        if (d2B <= radThr) myCnt += 0x10000;
    }
    __syncthreads();   // s_v / s_sd ready; protects s_redi
    int cntPk = blockRedSumI(myCnt, s_redi);

    // ---- per-row phases 2..6 (sequential, shared buffers) ----
    #pragma unroll 1
    for (int r = 0; r < 2; r++) {
        const int i  = i0 + r;
        const int bi = bi0 + r;
        const float* vrow = s_v + r*NN;
        float* prow = prow0 + (size_t)r*NN;
        int cnt = (r == 0) ? (cntPk & 0xFFFF) : (cntPk >> 16);

        // ---- phase 2: exact 24th-smallest d2 threshold (rare: cnt < 24) ----
        float thrAll = radThr;
        if (cnt < 24) {
            float last = -3.4e38f;
            int need = 24 - cnt;
            for (int k = 0; k < need; k++) {
                float lmin = 3.4e38f;
                #pragma unroll 8
                for (int s = 0; s < 32; s++) {
                    float v = vrow[t + s*NTH];
                    if (v > radThr && v > last) lmin = fminf(lmin, v);
                }
                last = blockRedMin(lmin, s_red);
            }
            thrAll = fmaxf(radThr, last);
        }

        // ---- phase 3: scan compaction of allowed set ----
        unsigned amask = 0;
        #pragma unroll 8
        for (int s = 0; s < 32; s++)
            if (vrow[t + s*NTH] <= thrAll) amask |= (1u << s);
        int myc = __popc(amask);

        int incl = myc;
        #pragma unroll
        for (int o = 1; o < 32; o <<= 1) {
            int nbr = __shfl_up_sync(0xffffffffu, incl, o);
            if (lane >= o) incl += nbr;
        }
        __syncthreads();
        if (lane == 31) s_w[warp] = incl;
        __syncthreads();
        int base = incl - myc;
        #pragma unroll
        for (int w = 0; w < 4; w++)
            if (w < warp) base += s_w[w];
        int m = (s_w[0] + s_w[1]) + (s_w[2] + s_w[3]);
        if (m > MAXL) m = MAXL;

        unsigned rem = amask;
        while (rem) {
            int s = __ffs(rem) - 1;
            rem &= rem - 1u;
            int j = t + s*NTH;
            if (base < MAXL) {
                s_list[base] = j;
                s_dist[base] = sqrtf(vrow[j]);
            }
            base++;
        }
        __syncthreads();

        // ---- phase 4: sparse sim + scores ----
        const float* tdb = g_tdt + (size_t)b*NN*CD;
        const float* tap = g_tadd + b*NN;
        const float4* sd4 = (const float4*)(s_sd + r*CD);
        for (int l = t; l < m; l += NTH) {
            int j = s_list[l];
            const float4* td4 = (const float4*)(tdb + (size_t)j*CD);
            float a0 = 0.f, a1 = 0.f, a2 = 0.f, a3 = 0.f;
            #pragma unroll
            for (int c = 0; c < CD/4; c++) {
                float4 x = sd4[c], y = td4[c];
                a0 = fmaf(x.x, y.x, a0);
                a1 = fmaf(x.y, y.y, a1);
                a2 = fmaf(x.z, y.z, a2);
                a3 = fmaf(x.w, y.w, a3);
            }
            float sim = (a0 + a1) + (a2 + a3);
            s_scr[l] = sim - s_dist[l] + tap[j];
        }
        __syncthreads();

        // ---- phase 5: softmax stats ----
        float lm = -3.4e38f;
        for (int l = t; l < m; l += NTH) lm = fmaxf(lm, s_scr[l]);
        float M = blockRedMax(lm, s_red);

        const float tinv = 1.0f / 0.07f;
        float pS = 0.f, pW = 0.f, pV0 = 0.f, pV1 = 0.f, pV2 = 0.f;
        for (int l = t; l < m; l += NTH) {
            float z = (s_scr[l] - M) * tinv;
            float e = __expf(z);
            s_scr[l] = e;
            pS += e;
            pW += e * z;
            int j = s_list[l];
            pV0 += e * lin16(j >> 8);
            pV1 += e * lin16((j >> 4) & 15);
            pV2 += e * lin16(j & 15);
        }
        float S  = blockRedSum(pS,  s_red);
        float W  = blockRedSum(pW,  s_red);
        float V0 = blockRedSum(pV0, s_red);
        float V1 = blockRedSum(pV1, s_red);
        float V2 = blockRedSum(pV2, s_red);

        float invS = 1.0f / S;

        // ---- phase 6: write normalized probs (scattered, few) + outputs ----
        for (int l = t; l < m; l += NTH) prow[s_list[l]] = s_scr[l] * invS;

        if (t == 0) {
            float e0 = V0 * invS, e1 = V1 * invS, e2 = V2 * invS;
            out[EXPOFF + (size_t)bi*3 + 0] = e0;
            out[EXPOFF + (size_t)bi*3 + 1] = e1;
            out[EXPOFF + (size_t)bi*3 + 2] = e2;
            float q0 = lin16(i >> 8), q1 = lin16((i >> 4) & 15), q2 = lin16(i & 15);
            out[DISPOFF + (size_t)b*3*NN + 0*NN + i] = e0 - q0;
            out[DISPOFF + (size_t)b*3*NN + 1*NN + i] = e1 - q1;
            out[DISPOFF + (size_t)b*3*NN + 2*NN + i] = e2 - q2;
            out[CONFOFF + bi] = g_smatch[bi] * invS;   // max prob is exactly 1/S
            out[ENTOFF  + bi] = logf(S) - W * invS;
        }
        __syncthreads();   // buffers reused by next row
    }
}

extern "C" void kernel_launch(void* const* d_in, const int* in_sizes, int n_in,
                              void* d_out, int out_size)
{
    const float* srcc  = (const float*)d_in[0];
    const float* tgtc  = (const float*)d_in[1];
    const float* sdesc = (const float*)d_in[2];
    const float* tdesc = (const float*)d_in[3];
    const float* sml   = (const float*)d_in[4];
    const float* tml   = (const float*)d_in[5];
    const float* tunc  = (const float*)d_in[7];
    float* out = (float*)d_out;

    // exact float boundary: largest v with sqrtf(v) <= 0.45f
    const float R = 0.45f;
    float radThr = R * R;
    while (sqrtf(radThr) > R) radThr = nextafterf(radThr, 0.0f);
    while (sqrtf(nextafterf(radThr, 1e30f)) <= R)
        radThr = nextafterf(radThr, 1e30f);

    kprep<<<(BB*NN + 255)/256, 256>>>(srcc, tgtc, sdesc, tdesc, sml, tml,
                                      tunc, out + SRCPOFF);
    dim3 grid(NN/2, BB);
    kmain<<<grid, NTH>>>(srcc, tgtc, out, radThr);
}

// round 9
// speedup vs baseline: 1.0347x; 1.0347x over previous
#include <cuda_runtime.h>
#include <math.h>

#define BB 2
#define NN 4096
#define CD 64
#define NTH 128
#define MAXL 512

// output layout offsets (floats), concatenated in reference return order
#define EXPOFF  0ull
#define DISPOFF 24576ull
#define POFF    49152ull
#define CONFOFF 33603584ull
#define ENTOFF  33611776ull
#define SRCPOFF 33619968ull

// scratch
__device__ float g_ssq[BB*NN];
__device__ float g_tsq[BB*NN];
__device__ float g_tadd[BB*NN];    // lml_j - 0.1*tu_j folded
__device__ float g_smatch[BB*NN];
__device__ float g_sdt[(size_t)BB*NN*CD];
__device__ float g_tdt[(size_t)BB*NN*CD];

__device__ __forceinline__ float lin16(int v) {
    return (float)(2*v - 15) * (1.0f/15.0f);
}

__device__ __forceinline__ float warpRedMax(float v){
    #pragma unroll
    for (int o = 16; o; o >>= 1) v = fmaxf(v, __shfl_xor_sync(0xffffffffu, v, o));
    return v;
}
__device__ __forceinline__ float warpRedMin(float v){
    #pragma unroll
    for (int o = 16; o; o >>= 1) v = fminf(v, __shfl_xor_sync(0xffffffffu, v, o));
    return v;
}
__device__ __forceinline__ float warpRedSum(float v){
    #pragma unroll
    for (int o = 16; o; o >>= 1) v += __shfl_xor_sync(0xffffffffu, v, o);
    return v;
}
__device__ __forceinline__ int warpRedSumI(int v){
    #pragma unroll
    for (int o = 16; o; o >>= 1) v += __shfl_xor_sync(0xffffffffu, v, o);
    return v;
}

__device__ __forceinline__ float blockRedMax(float v, float* sred){
    v = warpRedMax(v);
    __syncthreads();
    if ((threadIdx.x & 31) == 0) sred[threadIdx.x >> 5] = v;
    __syncthreads();
    return fmaxf(fmaxf(sred[0], sred[1]), fmaxf(sred[2], sred[3]));
}
__device__ __forceinline__ float blockRedMin(float v, float* sred){
    v = warpRedMin(v);
    __syncthreads();
    if ((threadIdx.x & 31) == 0) sred[threadIdx.x >> 5] = v;
    __syncthreads();
    return fminf(fminf(sred[0], sred[1]), fminf(sred[2], sred[3]));
}
__device__ __forceinline__ float blockRedSum(float v, float* sred){
    v = warpRedSum(v);
    __syncthreads();
    if ((threadIdx.x & 31) == 0) sred[threadIdx.x >> 5] = v;
    __syncthreads();
    return (sred[0] + sred[1]) + (sred[2] + sred[3]);
}
__device__ __forceinline__ int blockRedSumI(int v, int* sred){
    v = warpRedSumI(v);
    __syncthreads();
    if ((threadIdx.x & 31) == 0) sred[threadIdx.x >> 5] = v;
    __syncthreads();
    return (sred[0] + sred[1]) + (sred[2] + sred[3]);
}

__global__ __launch_bounds__(256)
void kprep(const float* __restrict__ srcc, const float* __restrict__ tgtc,
           const float* __restrict__ sdesc, const float* __restrict__ tdesc,
           const float* __restrict__ sml, const float* __restrict__ tml,
           const float* __restrict__ tunc,
           float* __restrict__ out_srcpos)
{
    int idx = blockIdx.x * blockDim.x + threadIdx.x;
    if (idx >= BB*NN) return;
    int b = idx / NN, n = idx % NN;

    const float* scp = srcc + (size_t)b*3*NN;
    float s0 = scp[n], s1 = scp[NN+n], s2 = scp[2*NN+n];
    g_ssq[idx] = fmaf(s2, s2, fmaf(s1, s1, s0*s0));

    const float* tcp = tgtc + (size_t)b*3*NN;
    float t0 = tcp[n], t1 = tcp[NN+n], t2 = tcp[2*NN+n];
    g_tsq[idx] = fmaf(t2, t2, fmaf(t1, t1, t0*t0));

    const float* sm = sml + (size_t)b*2*NN;
    g_smatch[idx] = 1.0f / (1.0f + expf(sm[NN+n] - sm[n]));
    const float* tm = tml + (size_t)b*2*NN;
    float p0 = 1.0f / (1.0f + expf(tm[NN+n] - tm[n]));
    g_tadd[idx] = fmaxf(logf(p0), -20.0f) - 0.1f * tunc[idx];

    // transpose descriptors: (B,C,N) -> (B,N,C) row-major, float4 writes
    const float* sdp = sdesc + (size_t)b*CD*NN + n;
    const float* tdp = tdesc + (size_t)b*CD*NN + n;
    float4* so = (float4*)(g_sdt + (size_t)idx*CD);
    float4* to = (float4*)(g_tdt + (size_t)idx*CD);
    #pragma unroll
    for (int c4 = 0; c4 < CD/4; c4++) {
        float4 v, w;
        v.x = sdp[(size_t)(4*c4+0)*NN]; w.x = tdp[(size_t)(4*c4+0)*NN];
        v.y = sdp[(size_t)(4*c4+1)*NN]; w.y = tdp[(size_t)(4*c4+1)*NN];
        v.z = sdp[(size_t)(4*c4+2)*NN]; w.z = tdp[(size_t)(4*c4+2)*NN];
        v.w = sdp[(size_t)(4*c4+3)*NN]; w.w = tdp[(size_t)(4*c4+3)*NN];
        so[c4] = v;
        to[c4] = w;
    }

    // src_pos output (constant voxel grid broadcast)
    int d = n >> 8, h = (n >> 4) & 15, w = n & 15;
    out_srcpos[(size_t)idx*3 + 0] = lin16(d);
    out_srcpos[(size_t)idx*3 + 1] = lin16(h);
    out_srcpos[(size_t)idx*3 + 2] = lin16(w);
}

__global__ __launch_bounds__(NTH, 8)
void kmain(const float* __restrict__ srcc, const float* __restrict__ tgtc,
           float* __restrict__ out, float radThr)
{
    const int i = blockIdx.x;
    const int b = blockIdx.y;
    const int t = threadIdx.x;
    const int lane = t & 31;
    const int warp = t >> 5;
    const int bi = b*NN + i;

    __shared__ float s_v[NN];          // full d2 row (clamped)
    __shared__ float s_sd[CD];
    __shared__ float s_red[4];
    __shared__ int   s_redi[4];
    __shared__ int   s_w[4];
    __shared__ int   s_list[MAXL];
    __shared__ float s_dist[MAXL];
    __shared__ float s_scr[MAXL];

    // ---- phase 0: zero probs row early (fire-and-forget DRAM writes) ----
    float* prow = out + POFF + (size_t)bi * NN;
    {
        float4 z4 = make_float4(0.f, 0.f, 0.f, 0.f);
        float4* p4 = (float4*)prow;
        #pragma unroll
        for (int s = 0; s < 8; s++) p4[t + s*NTH] = z4;
    }

    if (t < CD) s_sd[t] = g_sdt[(size_t)bi*CD + t];

    float sc0 = srcc[(size_t)b*3*NN + i];
    float sc1 = srcc[(size_t)b*3*NN + NN + i];
    float sc2 = srcc[(size_t)b*3*NN + 2*NN + i];
    float ssq = g_ssq[bi];

    const float* tcp  = tgtc + (size_t)b*3*NN;
    const float* tsqp = g_tsq + b*NN;

    // ---- phase 1: d2 row -> shared, build radius mask inline ----
    unsigned amask = 0;
    #pragma unroll 4
    for (int s = 0; s < 32; s++) {
        int j = t + s*NTH;
        float u0 = tcp[j], u1 = tcp[NN+j], u2 = tcp[2*NN+j];
        float dot = fmaf(sc2, u2, fmaf(sc1, u1, sc0*u0));
        float d2  = fmaf(-2.0f, dot, ssq + tsqp[j]);
        float d2c = fmaxf(d2, 1e-12f);
        s_v[j] = d2c;
        if (d2c <= radThr) amask |= (1u << s);
    }
    __syncthreads();   // s_v / s_sd ready; protects s_redi
    int cnt = blockRedSumI(__popc(amask), s_redi);

    // ---- phase 2+3a: if radius count < 24 (rare, ~0.7%), widen the mask ----
    if (cnt < 24) {
        float last = -3.4e38f;
        int need = 24 - cnt;
        for (int k = 0; k < need; k++) {
            float lmin = 3.4e38f;
            #pragma unroll 8
            for (int s = 0; s < 32; s++) {
                float v = s_v[t + s*NTH];
                if (v > radThr && v > last) lmin = fminf(lmin, v);
            }
            last = blockRedMin(lmin, s_red);
        }
        float thrAll = fmaxf(radThr, last);
        amask = 0;
        #pragma unroll 8
        for (int s = 0; s < 32; s++)
            if (s_v[t + s*NTH] <= thrAll) amask |= (1u << s);
    }
    // common path (cnt >= 24): amask from phase 1 IS the allowed set

    // ---- phase 3b: scan compaction of allowed set ----
    int myc = __popc(amask);
    int incl = myc;
    #pragma unroll
    for (int o = 1; o < 32; o <<= 1) {
        int nbr = __shfl_up_sync(0xffffffffu, incl, o);
        if (lane >= o) incl += nbr;
    }
    __syncthreads();
    if (lane == 31) s_w[warp] = incl;
    __syncthreads();
    int base = incl - myc;
    #pragma unroll
    for (int w = 0; w < 4; w++)
        if (w < warp) base += s_w[w];
    int m = (s_w[0] + s_w[1]) + (s_w[2] + s_w[3]);
    if (m > MAXL) m = MAXL;

    unsigned rem = amask;
    while (rem) {
        int s = __ffs(rem) - 1;
        rem &= rem - 1u;
        int j = t + s*NTH;
        if (base < MAXL) {
            s_list[base] = j;
            s_dist[base] = sqrtf(s_v[j]);
        }
        base++;
    }
    __syncthreads();

    // ---- phase 4: sparse sim + scores ----
    const float* tdb = g_tdt + (size_t)b*NN*CD;
    const float* tap = g_tadd + b*NN;
    for (int l = t; l < m; l += NTH) {
        int j = s_list[l];
        const float4* td4 = (const float4*)(tdb + (size_t)j*CD);
        const float4* sd4 = (const float4*)s_sd;
        float a0 = 0.f, a1 = 0.f, a2 = 0.f, a3 = 0.f;
        #pragma unroll
        for (int c = 0; c < CD/4; c++) {
            float4 x = sd4[c], y = td4[c];
            a0 = fmaf(x.x, y.x, a0);
            a1 = fmaf(x.y, y.y, a1);
            a2 = fmaf(x.z, y.z, a2);
            a3 = fmaf(x.w, y.w, a3);
        }
        float sim = (a0 + a1) + (a2 + a3);
        s_scr[l] = sim - s_dist[l] + tap[j];
    }
    __syncthreads();

    // ---- phase 5: softmax stats ----
    float lm = -3.4e38f;
    for (int l = t; l < m; l += NTH) lm = fmaxf(lm, s_scr[l]);
    float M = blockRedMax(lm, s_red);

    const float tinv = 1.0f / 0.07f;
    float pS = 0.f, pW = 0.f, pV0 = 0.f, pV1 = 0.f, pV2 = 0.f;
    for (int l = t; l < m; l += NTH) {
        float z = (s_scr[l] - M) * tinv;
        float e = __expf(z);
        s_scr[l] = e;
        pS += e;
        pW += e * z;
        int j = s_list[l];
        pV0 += e * lin16(j >> 8);
        pV1 += e * lin16((j >> 4) & 15);
        pV2 += e * lin16(j & 15);
    }
    float S  = blockRedSum(pS,  s_red);
    float W  = blockRedSum(pW,  s_red);
    float V0 = blockRedSum(pV0, s_red);
    float V1 = blockRedSum(pV1, s_red);
    float V2 = blockRedSum(pV2, s_red);

    float invS = 1.0f / S;

    // ---- phase 6: write normalized probs (scattered, few) + outputs ----
    for (int l = t; l < m; l += NTH) prow[s_list[l]] = s_scr[l] * invS;

    if (t == 0) {
        float e0 = V0 * invS, e1 = V1 * invS, e2 = V2 * invS;
        out[EXPOFF + (size_t)bi*3 + 0] = e0;
        out[EXPOFF + (size_t)bi*3 + 1] = e1;
        out[EXPOFF + (size_t)bi*3 + 2] = e2;
        float q0 = lin16(i >> 8), q1 = lin16((i >> 4) & 15), q2 = lin16(i & 15);
        out[DISPOFF + (size_t)b*3*NN + 0*NN + i] = e0 - q0;
        out[DISPOFF + (size_t)b*3*NN + 1*NN + i] = e1 - q1;
        out[DISPOFF + (size_t)b*3*NN + 2*NN + i] = e2 - q2;
        out[CONFOFF + bi] = g_smatch[bi] * invS;   // max prob is exactly 1/S
        out[ENTOFF  + bi] = logf(S) - W * invS;
    }
}

extern "C" void kernel_launch(void* const* d_in, const int* in_sizes, int n_in,
                              void* d_out, int out_size)
{
    const float* srcc  = (const float*)d_in[0];
    const float* tgtc  = (const float*)d_in[1];
    const float* sdesc = (const float*)d_in[2];
    const float* tdesc = (const float*)d_in[3];
    const float* sml   = (const float*)d_in[4];
    const float* tml   = (const float*)d_in[5];
    const float* tunc  = (const float*)d_in[7];
    float* out = (float*)d_out;

    // exact float boundary: largest v with sqrtf(v) <= 0.45f
    const float R = 0.45f;
    float radThr = R * R;
    while (sqrtf(radThr) > R) radThr = nextafterf(radThr, 0.0f);
    while (sqrtf(nextafterf(radThr, 1e30f)) <= R)
        radThr = nextafterf(radThr, 1e30f);

    kprep<<<(BB*NN + 255)/256, 256>>>(srcc, tgtc, sdesc, tdesc, sml, tml,
                                      tunc, out + SRCPOFF);
    dim3 grid(NN, BB);
    kmain<<<grid, NTH>>>(srcc, tgtc, out, radThr);
}